// round 16
// baseline (speedup 1.0000x reference)
#include <cuda_runtime.h>
#include <cuda_bf16.h>

#define NN 100000
#define EE 1600000
#define NT 391            // node tiles of 256

#define MMA_TF32(d0,d1,d2,d3,a0,a1,a2,a3,b0,b1) \
    asm("mma.sync.aligned.m16n8k8.row.col.f32.tf32.tf32.f32 " \
        "{%0,%1,%2,%3},{%4,%5,%6,%7},{%8,%9},{%0,%1,%2,%3};" \
        : "+f"(d0), "+f"(d1), "+f"(d2), "+f"(d3) \
        : "r"(a0), "r"(a1), "r"(a2), "r"(a3), "r"(b0), "r"(b1))

__device__ __forceinline__ unsigned cvt_tf32(float f) {
    unsigned u;
    asm("cvt.rna.tf32.f32 %0, %1;" : "=r"(u) : "f"(f));
    return u;
}

// ---- device scratch (no allocation) ----
__device__ float g_Atb2[64 * 192];              // composed head weights (k,q pre-scaled 0.5)
__device__ float g_bh[3 * 64];                  // composed head biases
__device__ float g_u1[64];
__device__ float g_c1;
__device__ float g_vsum[NN];                    // per-node sum of vw (fp32)
__device__ __nv_bfloat16 g_kh[(size_t)NN * 64]; // holds 0.5*k
__device__ __nv_bfloat16 g_qh[(size_t)NN * 64]; // holds 0.5*q
__device__ __nv_bfloat16 g_vh[(size_t)NN * 64]; // holds vw

// ---------------- prologue: compose weights ----------------
__global__ __launch_bounds__(256)
void prec(const float* __restrict__ W2, const float* __restrict__ b2,
          const float* __restrict__ Wk, const float* __restrict__ bk,
          const float* __restrict__ Wq, const float* __restrict__ bq,
          const float* __restrict__ Wv, const float* __restrict__ bv,
          const float* __restrict__ Ws, const float* __restrict__ b_gate,
          const float* __restrict__ Wsc, const float* __restrict__ bsc)
{
    const int tid = threadIdx.x;
    const int blk = blockIdx.x;

    if (blk < 12) {
        const int h = blk >> 2, q = blk & 3;
        __shared__ float wht[65 * 64];
        __shared__ float w2q[16 * 64];
        __shared__ float wscs[64];
        const float* Wh = h == 0 ? Wk : h == 1 ? Wq : Wv;
        for (int idx = tid; idx < 4096; idx += 256) {
            int r = idx >> 6, c = idx & 63;
            wht[c * 65 + r] = Wh[idx];
        }
        for (int idx = tid; idx < 1024; idx += 256) {
            int j = idx >> 4, ls = idx & 15;
            w2q[idx] = W2[j * 64 + q * 16 + ls];
        }
        if (tid < 64) wscs[tid] = Wsc[tid];
        __syncthreads();

        const int i = tid & 63;
        const int lsub = tid >> 6;
        float acc[4] = {0.f, 0.f, 0.f, 0.f};
        for (int j = 0; j < 64; j++) {
            float wv = wht[j * 65 + i];
            acc[0] = fmaf(wv, w2q[j * 16 + lsub + 0],  acc[0]);
            acc[1] = fmaf(wv, w2q[j * 16 + lsub + 4],  acc[1]);
            acc[2] = fmaf(wv, w2q[j * 16 + lsub + 8],  acc[2]);
            acc[3] = fmaf(wv, w2q[j * 16 + lsub + 12], acc[3]);
        }
        float scale = (h == 2) ? wscs[i] : 0.5f;   // k,q pre-scaled for tanh arg
        #pragma unroll
        for (int t = 0; t < 4; t++) {
            int l = q * 16 + lsub + 4 * t;
            g_Atb2[l * 192 + h * 64 + i] = __uint_as_float(cvt_tf32(acc[t] * scale));
        }
    } else if (blk < 15) {
        const int h = blk - 12;
        __shared__ float whs[65 * 64];
        __shared__ float b2s[64], wscs[64], part[256];
        const float* Wh = h == 0 ? Wk : h == 1 ? Wq : Wv;
        for (int idx = tid; idx < 4096; idx += 256) {
            int r = idx >> 6, c = idx & 63;
            whs[c * 65 + r] = Wh[idx];
        }
        if (tid < 64) { b2s[tid] = b2[tid]; wscs[tid] = Wsc[tid]; }
        __syncthreads();
        const int i = tid & 63, jg = tid >> 6;
        float s = 0.f;
        #pragma unroll
        for (int jj = 0; jj < 16; jj++) {
            int j = jg * 16 + jj;
            s = fmaf(whs[j * 65 + i], b2s[j], s);
        }
        part[jg * 64 + i] = s;
        __syncthreads();
        if (tid < 64) {
            const float* bh_in = h == 0 ? bk : h == 1 ? bq : bv;
            float v = bh_in[tid] + part[tid] + part[64 + tid] + part[128 + tid] + part[192 + tid];
            g_bh[h * 64 + tid] = (h == 2) ? v * wscs[tid] : v * 0.5f;
        }
    } else {
        __shared__ float part[256], uls[64], csum[64];
        const int l = tid & 63, jg = tid >> 6;
        float s = 0.f;
        #pragma unroll
        for (int jj = 0; jj < 16; jj++) {
            int j = jg * 16 + jj;
            s = fmaf(Wsc[j], Ws[j * 64 + l], s);
        }
        part[jg * 64 + l] = s;
        __syncthreads();
        if (tid < 64) uls[tid] = part[tid] + part[64 + tid] + part[128 + tid] + part[192 + tid];
        __syncthreads();
        float t2 = 0.f;
        #pragma unroll
        for (int ll = 0; ll < 16; ll++) {
            int lv = jg * 16 + ll;
            t2 = fmaf(uls[lv], W2[lv * 64 + l], t2);
        }
        part[jg * 64 + l] = t2;
        __syncthreads();
        if (tid < 64) {
            g_u1[tid] = part[tid] + part[64 + tid] + part[128 + tid] + part[192 + tid];
            csum[tid] = fmaf(Wsc[tid], b_gate[tid], uls[tid] * b2[tid]);
        }
        __syncthreads();
        if (tid == 0) {
            float c = bsc[0];
            for (int j = 0; j < 64; j++) c += csum[j];
            g_c1 = c;
        }
    }
}

__device__ __forceinline__ unsigned pack_bf2(float a, float b) {
    __nv_bfloat162 h = __floats2bfloat162_rn(a, b);
    return *reinterpret_cast<unsigned*>(&h);
}

// ---------------- fused persistent node kernel: ALL-tf32-mma (exact R15) ----------------
__global__ __launch_bounds__(512, 1)
void node_fused(const float* __restrict__ x,
                const float* __restrict__ W1, const float* __restrict__ b1,
                float* __restrict__ out)
{
    extern __shared__ float sm[];
    float* w1b  = sm;                // 9216 : W1 tf32, [k=128][stride 72]
    float* bb   = w1b + 9216;        // 320  : b1(64) | u1(64) | bh(192)
    float* atb2 = bb + 320;          // 12800: At tf32 [l=64][stride 200]
    float* xa   = atb2 + 12800;      // 17408: x tf32 [node=256][stride 68]
    float* hsf  = xa;                // alias: h1 tf32 [node=256][stride 65]

    const int tid = threadIdx.x;
    const int tw = tid >> 5;
    const int lane = tid & 31;
    const int l4 = lane >> 2, lm4 = lane & 3;

    for (int idx = tid; idx < 8192; idx += 512) {
        int i = idx >> 7, k = idx & 127;
        w1b[k * 72 + i] = __uint_as_float(cvt_tf32(W1[idx]));
    }
    for (int idx = tid; idx < 12288; idx += 512)
        atb2[(idx / 192) * 200 + idx % 192] = g_Atb2[idx];
    if (tid < 64) {
        bb[tid]      = b1[tid];
        bb[64 + tid] = g_u1[tid];
    }
    if (tid < 192) bb[128 + tid] = g_bh[tid];
    const float c1 = g_c1;
    __syncthreads();

    for (int tile = blockIdx.x; tile < NT; tile += gridDim.x) {
        const int base = tile * 256;

        // ---- layer 1: tf32 mma ----
        float acc[8][4];
        #pragma unroll
        for (int nt = 0; nt < 8; nt++) {
            float2 bias = *(const float2*)(bb + nt * 8 + lm4 * 2);
            acc[nt][0] = bias.x; acc[nt][1] = bias.y;
            acc[nt][2] = bias.x; acc[nt][3] = bias.y;
        }

        #pragma unroll 1
        for (int half = 0; half < 2; half++) {
            __syncthreads();
            #pragma unroll
            for (int idx = tid; idx < 4096; idx += 512) {
                int n = idx >> 4, k4 = idx & 15;
                int nn = base + n;
                float4 v = (nn < NN) ? ((const float4*)x)[(size_t)nn * 32 + half * 16 + k4]
                                     : make_float4(0.f, 0.f, 0.f, 0.f);
                float* d = xa + n * 68 + k4 * 4;
                d[0] = __uint_as_float(cvt_tf32(v.x));
                d[1] = __uint_as_float(cvt_tf32(v.y));
                d[2] = __uint_as_float(cvt_tf32(v.z));
                d[3] = __uint_as_float(cvt_tf32(v.w));
            }
            __syncthreads();
            const float* xr = xa + (tw * 16 + l4) * 68;
            #pragma unroll
            for (int ks = 0; ks < 8; ks++) {
                int cc = ks * 8 + lm4;
                unsigned a0 = __float_as_uint(xr[cc]);
                unsigned a1 = __float_as_uint(xr[8 * 68 + cc]);
                unsigned a2 = __float_as_uint(xr[cc + 4]);
                unsigned a3 = __float_as_uint(xr[8 * 68 + cc + 4]);
                int kg = half * 64 + ks * 8 + lm4;
                const float* bcol = w1b + kg * 72;
                #pragma unroll
                for (int nt = 0; nt < 8; nt++) {
                    unsigned b0 = __float_as_uint(bcol[nt * 8 + l4]);
                    unsigned b1f = __float_as_uint(bcol[4 * 72 + nt * 8 + l4]);
                    MMA_TF32(acc[nt][0], acc[nt][1], acc[nt][2], acc[nt][3],
                             a0, a1, a2, a3, b0, b1f);
                }
            }
        }

        // ---- relu + score from fragments ----
        float sc0 = 0.f, sc1 = 0.f;
        #pragma unroll
        for (int nt = 0; nt < 8; nt++) {
            int col0 = nt * 8 + lm4 * 2;
            float u0 = bb[64 + col0], u1v = bb[64 + col0 + 1];
            acc[nt][0] = fmaxf(acc[nt][0], 0.f);
            acc[nt][1] = fmaxf(acc[nt][1], 0.f);
            acc[nt][2] = fmaxf(acc[nt][2], 0.f);
            acc[nt][3] = fmaxf(acc[nt][3], 0.f);
            sc0 = fmaf(acc[nt][0], u0, fmaf(acc[nt][1], u1v, sc0));
            sc1 = fmaf(acc[nt][2], u0, fmaf(acc[nt][3], u1v, sc1));
        }
        sc0 += __shfl_down_sync(0xffffffffu, sc0, 2, 4);
        sc0 += __shfl_down_sync(0xffffffffu, sc0, 1, 4);
        sc1 += __shfl_down_sync(0xffffffffu, sc1, 2, 4);
        sc1 += __shfl_down_sync(0xffffffffu, sc1, 1, 4);
        if (lm4 == 0) {
            int node = base + tw * 16 + l4;
            if (node < NN)     out[node]     = sc0 + c1;
            if (node + 8 < NN) out[node + 8] = sc1 + c1;
        }

        // ---- write h1 (tf32) to smem — scalar stores (stride 65 is odd) ----
        __syncthreads();
        {
            float* h0 = hsf + (tw * 16 + l4) * 65;
            float* h8 = h0 + 8 * 65;
            #pragma unroll
            for (int nt = 0; nt < 8; nt++) {
                int col0 = nt * 8 + lm4 * 2;
                h0[col0]     = __uint_as_float(cvt_tf32(acc[nt][0]));
                h0[col0 + 1] = __uint_as_float(cvt_tf32(acc[nt][1]));
                h8[col0]     = __uint_as_float(cvt_tf32(acc[nt][2]));
                h8[col0 + 1] = __uint_as_float(cvt_tf32(acc[nt][3]));
            }
        }
        __syncthreads();

        // ---- heads: 16 warps = (m-pair mp, n-half nh) ----
        {
            const int mp = tw & 7, nh = tw >> 3;
            unsigned Af[2][8][4];
            #pragma unroll
            for (int mt = 0; mt < 2; mt++) {
                const float* h0 = hsf + (mp * 32 + mt * 16 + l4) * 65;
                const float* h1r = h0 + 8 * 65;
                #pragma unroll
                for (int ks = 0; ks < 8; ks++) {
                    int cc = ks * 8 + lm4;
                    Af[mt][ks][0] = __float_as_uint(h0[cc]);
                    Af[mt][ks][1] = __float_as_uint(h1r[cc]);
                    Af[mt][ks][2] = __float_as_uint(h0[cc + 4]);
                    Af[mt][ks][3] = __float_as_uint(h1r[cc + 4]);
                }
            }
            const int n0g = base + mp * 32 + l4;
            float vs[4] = {0.f, 0.f, 0.f, 0.f};
            #pragma unroll 1
            for (int nt = nh * 12; nt < nh * 12 + 12; nt++) {
                int f192 = nt * 8 + 2 * lm4;
                float2 bias = *(const float2*)(bb + 128 + f192);
                unsigned Bf[8][2];
                const float* bcol = atb2 + nt * 8 + l4;
                #pragma unroll
                for (int ks = 0; ks < 8; ks++) {
                    Bf[ks][0] = __float_as_uint(bcol[(ks * 8 + lm4) * 200]);
                    Bf[ks][1] = __float_as_uint(bcol[(ks * 8 + lm4 + 4) * 200]);
                }
                __nv_bfloat16* dp = (f192 < 64) ? g_kh : (f192 < 128) ? g_qh : g_vh;
                int feat = f192 & 63;
                #pragma unroll
                for (int mt = 0; mt < 2; mt++) {
                    float d0 = bias.x, d1 = bias.y, d2 = bias.x, d3 = bias.y;
                    #pragma unroll
                    for (int ks = 0; ks < 8; ks++)
                        MMA_TF32(d0, d1, d2, d3,
                                 Af[mt][ks][0], Af[mt][ks][1], Af[mt][ks][2], Af[mt][ks][3],
                                 Bf[ks][0], Bf[ks][1]);
                    if (f192 >= 128) {
                        vs[mt * 2]     += d0 + d1;
                        vs[mt * 2 + 1] += d2 + d3;
                    }
                    int node = n0g + mt * 16;
                    if (node < NN)
                        *(unsigned*)(dp + (size_t)node * 64 + feat) = pack_bf2(d0, d1);
                    if (node + 8 < NN)
                        *(unsigned*)(dp + (size_t)(node + 8) * 64 + feat) = pack_bf2(d2, d3);
                }
            }
            if (nh == 1) {
                #pragma unroll
                for (int t = 0; t < 4; t++) {
                    vs[t] += __shfl_down_sync(0xffffffffu, vs[t], 2, 4);
                    vs[t] += __shfl_down_sync(0xffffffffu, vs[t], 1, 4);
                }
                if (lm4 == 0) {
                    #pragma unroll
                    for (int mt = 0; mt < 2; mt++) {
                        int node = n0g + mt * 16;
                        if (node < NN)     g_vsum[node]     = vs[mt * 2];
                        if (node + 8 < NN) g_vsum[node + 8] = vs[mt * 2 + 1];
                    }
                }
            }
        }
    }
}

// ---------------- edge kernel: 8 lanes/edge, full-line gathers, bf16x2 gate ----------------
__device__ __forceinline__ float2 bf2f(unsigned u) {
    __nv_bfloat162 h = *reinterpret_cast<__nv_bfloat162*>(&u);
    return __bfloat1622float2(h);
}
__device__ __forceinline__ void pair2(unsigned ku, unsigned qu, unsigned vu, float& acc) {
    __nv_bfloat162 k2 = *reinterpret_cast<__nv_bfloat162*>(&ku);
    __nv_bfloat162 q2 = *reinterpret_cast<__nv_bfloat162*>(&qu);
    __nv_bfloat162 s2 = __hadd2(k2, q2);
    unsigned su = *reinterpret_cast<unsigned*>(&s2);
    unsigned tu;
    asm("tanh.approx.bf16x2 %0, %1;" : "=r"(tu) : "r"(su));
    float2 tf = bf2f(tu);
    float2 vf = bf2f(vu);
    acc = fmaf(tf.x, vf.x, acc);
    acc = fmaf(tf.y, vf.y, acc);
}

__global__ __launch_bounds__(256)
void edge_kernel(const int* __restrict__ ei, float* __restrict__ out)
{
    int t = blockIdx.x * 256 + threadIdx.x;
    int e = t >> 3;
    if (e >= EE) return;
    int sub = t & 7;

    int src = ei[e];
    int dst = ei[EE + e];

    // one uint4 per lane: 8 lanes cover the full 128B row of each array
    uint4 kk = *(const uint4*)(g_kh + (size_t)dst * 64 + sub * 8);
    uint4 qq = *(const uint4*)(g_qh + (size_t)src * 64 + sub * 8);
    uint4 vv = *(const uint4*)(g_vh + (size_t)src * 64 + sub * 8);

    float a0 = 0.f, a1 = 0.f;
    pair2(kk.x, qq.x, vv.x, a0);
    pair2(kk.y, qq.y, vv.y, a1);
    pair2(kk.z, qq.z, vv.z, a0);
    pair2(kk.w, qq.w, vv.w, a1);
    float s = a0 + a1;

    s += __shfl_down_sync(0xffffffffu, s, 4, 8);
    s += __shfl_down_sync(0xffffffffu, s, 2, 8);
    s += __shfl_down_sync(0xffffffffu, s, 1, 8);
    if (sub == 0) {
        // message = 0.5*(sum t.v + sum v)
        atomicAdd(out + dst, 0.5f * (s + g_vsum[src]));
    }
}

extern "C" void kernel_launch(void* const* d_in, const int* in_sizes, int n_in,
                              void* d_out, int out_size)
{
    const float* x      = (const float*)d_in[0];
    const int*   ei     = (const int*)d_in[1];
    const float* W1     = (const float*)d_in[2];
    const float* b1     = (const float*)d_in[3];
    const float* W2     = (const float*)d_in[4];
    const float* b2     = (const float*)d_in[5];
    const float* Wk     = (const float*)d_in[6];
    const float* bk     = (const float*)d_in[7];
    const float* Wq     = (const float*)d_in[8];
    const float* bq     = (const float*)d_in[9];
    const float* Wv     = (const float*)d_in[10];
    const float* bv     = (const float*)d_in[11];
    const float* Ws     = (const float*)d_in[12];
    const float* b_gate = (const float*)d_in[13];
    const float* Wsc    = (const float*)d_in[14];
    const float* bsc    = (const float*)d_in[15];
    float* out = (float*)d_out;

    size_t smemf = 39744 * sizeof(float);   // 155.3 KB
    cudaFuncSetAttribute(node_fused, cudaFuncAttributeMaxDynamicSharedMemorySize, (int)smemf);

    prec<<<16, 256>>>(W2, b2, Wk, bk, Wq, bq, Wv, bv, Ws, b_gate, Wsc, bsc);
    node_fused<<<148, 512, smemf>>>(x, W1, b1, out);
    edge_kernel<<<(EE * 8) / 256, 256>>>(ei, out);   // 50000 blocks
}

// round 17
// speedup vs baseline: 1.2639x; 1.2639x over previous
#include <cuda_runtime.h>
#include <cuda_bf16.h>
#include <cuda_fp16.h>

#define NN 100000
#define EE 1600000
#define NT 391            // node tiles of 256

#define MMA_TF32(d0,d1,d2,d3,a0,a1,a2,a3,b0,b1) \
    asm("mma.sync.aligned.m16n8k8.row.col.f32.tf32.tf32.f32 " \
        "{%0,%1,%2,%3},{%4,%5,%6,%7},{%8,%9},{%0,%1,%2,%3};" \
        : "+f"(d0), "+f"(d1), "+f"(d2), "+f"(d3) \
        : "r"(a0), "r"(a1), "r"(a2), "r"(a3), "r"(b0), "r"(b1))

__device__ __forceinline__ unsigned cvt_tf32(float f) {
    unsigned u;
    asm("cvt.rna.tf32.f32 %0, %1;" : "=r"(u) : "f"(f));
    return u;
}

// ---- device scratch (no allocation) ----
__device__ float g_Atb2[64 * 192];              // composed head weights (k,q pre-scaled 0.5)
__device__ float g_bh[3 * 64];                  // composed head biases
__device__ float g_u1[64];
__device__ float g_c1;
__device__ float g_vsum[NN];                    // per-node sum of vw (fp32, exact)
__device__ __align__(16) unsigned char g_k8[(size_t)NN * 64];  // 0.5*k, e4m3
__device__ __align__(16) unsigned char g_q8[(size_t)NN * 64];  // 0.5*q, e4m3
__device__ __align__(16) __half g_vh[(size_t)NN * 64];          // vw, f16

// ---------------- prologue: compose weights (unchanged) ----------------
__global__ __launch_bounds__(256)
void prec(const float* __restrict__ W2, const float* __restrict__ b2,
          const float* __restrict__ Wk, const float* __restrict__ bk,
          const float* __restrict__ Wq, const float* __restrict__ bq,
          const float* __restrict__ Wv, const float* __restrict__ bv,
          const float* __restrict__ Ws, const float* __restrict__ b_gate,
          const float* __restrict__ Wsc, const float* __restrict__ bsc)
{
    const int tid = threadIdx.x;
    const int blk = blockIdx.x;

    if (blk < 12) {
        const int h = blk >> 2, q = blk & 3;
        __shared__ float wht[65 * 64];
        __shared__ float w2q[16 * 64];
        __shared__ float wscs[64];
        const float* Wh = h == 0 ? Wk : h == 1 ? Wq : Wv;
        for (int idx = tid; idx < 4096; idx += 256) {
            int r = idx >> 6, c = idx & 63;
            wht[c * 65 + r] = Wh[idx];
        }
        for (int idx = tid; idx < 1024; idx += 256) {
            int j = idx >> 4, ls = idx & 15;
            w2q[idx] = W2[j * 64 + q * 16 + ls];
        }
        if (tid < 64) wscs[tid] = Wsc[tid];
        __syncthreads();

        const int i = tid & 63;
        const int lsub = tid >> 6;
        float acc[4] = {0.f, 0.f, 0.f, 0.f};
        for (int j = 0; j < 64; j++) {
            float wv = wht[j * 65 + i];
            acc[0] = fmaf(wv, w2q[j * 16 + lsub + 0],  acc[0]);
            acc[1] = fmaf(wv, w2q[j * 16 + lsub + 4],  acc[1]);
            acc[2] = fmaf(wv, w2q[j * 16 + lsub + 8],  acc[2]);
            acc[3] = fmaf(wv, w2q[j * 16 + lsub + 12], acc[3]);
        }
        float scale = (h == 2) ? wscs[i] : 0.5f;
        #pragma unroll
        for (int t = 0; t < 4; t++) {
            int l = q * 16 + lsub + 4 * t;
            g_Atb2[l * 192 + h * 64 + i] = __uint_as_float(cvt_tf32(acc[t] * scale));
        }
    } else if (blk < 15) {
        const int h = blk - 12;
        __shared__ float whs[65 * 64];
        __shared__ float b2s[64], wscs[64], part[256];
        const float* Wh = h == 0 ? Wk : h == 1 ? Wq : Wv;
        for (int idx = tid; idx < 4096; idx += 256) {
            int r = idx >> 6, c = idx & 63;
            whs[c * 65 + r] = Wh[idx];
        }
        if (tid < 64) { b2s[tid] = b2[tid]; wscs[tid] = Wsc[tid]; }
        __syncthreads();
        const int i = tid & 63, jg = tid >> 6;
        float s = 0.f;
        #pragma unroll
        for (int jj = 0; jj < 16; jj++) {
            int j = jg * 16 + jj;
            s = fmaf(whs[j * 65 + i], b2s[j], s);
        }
        part[jg * 64 + i] = s;
        __syncthreads();
        if (tid < 64) {
            const float* bh_in = h == 0 ? bk : h == 1 ? bq : bv;
            float v = bh_in[tid] + part[tid] + part[64 + tid] + part[128 + tid] + part[192 + tid];
            g_bh[h * 64 + tid] = (h == 2) ? v * wscs[tid] : v * 0.5f;
        }
    } else {
        __shared__ float part[256], uls[64], csum[64];
        const int l = tid & 63, jg = tid >> 6;
        float s = 0.f;
        #pragma unroll
        for (int jj = 0; jj < 16; jj++) {
            int j = jg * 16 + jj;
            s = fmaf(Wsc[j], Ws[j * 64 + l], s);
        }
        part[jg * 64 + l] = s;
        __syncthreads();
        if (tid < 64) uls[tid] = part[tid] + part[64 + tid] + part[128 + tid] + part[192 + tid];
        __syncthreads();
        float t2 = 0.f;
        #pragma unroll
        for (int ll = 0; ll < 16; ll++) {
            int lv = jg * 16 + ll;
            t2 = fmaf(uls[lv], W2[lv * 64 + l], t2);
        }
        part[jg * 64 + l] = t2;
        __syncthreads();
        if (tid < 64) {
            g_u1[tid] = part[tid] + part[64 + tid] + part[128 + tid] + part[192 + tid];
            csum[tid] = fmaf(Wsc[tid], b_gate[tid], uls[tid] * b2[tid]);
        }
        __syncthreads();
        if (tid == 0) {
            float c = bsc[0];
            for (int j = 0; j < 64; j++) c += csum[j];
            g_c1 = c;
        }
    }
}

__device__ __forceinline__ unsigned short pack_e4m3x2(float lo, float hi) {
    unsigned short p;
    asm("cvt.rn.satfinite.e4m3x2.f32 %0, %1, %2;" : "=h"(p) : "f"(hi), "f"(lo));
    return p;
}
__device__ __forceinline__ unsigned pack_h2(float a, float b) {
    __half2 h = __floats2half2_rn(a, b);
    return *reinterpret_cast<unsigned*>(&h);
}

// ---------------- fused persistent node kernel: ALL-tf32-mma ----------------
__global__ __launch_bounds__(512, 1)
void node_fused(const float* __restrict__ x,
                const float* __restrict__ W1, const float* __restrict__ b1,
                float* __restrict__ out)
{
    extern __shared__ float sm[];
    float* w1b  = sm;                // 9216 : W1 tf32, [k=128][stride 72]
    float* bb   = w1b + 9216;        // 320  : b1(64) | u1(64) | bh(192)
    float* atb2 = bb + 320;          // 12800: At tf32 [l=64][stride 200]
    float* xa   = atb2 + 12800;      // 17408: x tf32 [node=256][stride 68]
    float* hsf  = xa;                // alias: h1 tf32 [node=256][stride 65]

    const int tid = threadIdx.x;
    const int tw = tid >> 5;
    const int lane = tid & 31;
    const int l4 = lane >> 2, lm4 = lane & 3;

    for (int idx = tid; idx < 8192; idx += 512) {
        int i = idx >> 7, k = idx & 127;
        w1b[k * 72 + i] = __uint_as_float(cvt_tf32(W1[idx]));
    }
    for (int idx = tid; idx < 12288; idx += 512)
        atb2[(idx / 192) * 200 + idx % 192] = g_Atb2[idx];
    if (tid < 64) {
        bb[tid]      = b1[tid];
        bb[64 + tid] = g_u1[tid];
    }
    if (tid < 192) bb[128 + tid] = g_bh[tid];
    const float c1 = g_c1;
    __syncthreads();

    for (int tile = blockIdx.x; tile < NT; tile += gridDim.x) {
        const int base = tile * 256;

        // ---- layer 1: tf32 mma ----
        float acc[8][4];
        #pragma unroll
        for (int nt = 0; nt < 8; nt++) {
            float2 bias = *(const float2*)(bb + nt * 8 + lm4 * 2);
            acc[nt][0] = bias.x; acc[nt][1] = bias.y;
            acc[nt][2] = bias.x; acc[nt][3] = bias.y;
        }

        #pragma unroll 1
        for (int half = 0; half < 2; half++) {
            __syncthreads();
            #pragma unroll
            for (int idx = tid; idx < 4096; idx += 512) {
                int n = idx >> 4, k4 = idx & 15;
                int nn = base + n;
                float4 v = (nn < NN) ? ((const float4*)x)[(size_t)nn * 32 + half * 16 + k4]
                                     : make_float4(0.f, 0.f, 0.f, 0.f);
                float* d = xa + n * 68 + k4 * 4;
                d[0] = __uint_as_float(cvt_tf32(v.x));
                d[1] = __uint_as_float(cvt_tf32(v.y));
                d[2] = __uint_as_float(cvt_tf32(v.z));
                d[3] = __uint_as_float(cvt_tf32(v.w));
            }
            __syncthreads();
            const float* xr = xa + (tw * 16 + l4) * 68;
            #pragma unroll
            for (int ks = 0; ks < 8; ks++) {
                int cc = ks * 8 + lm4;
                unsigned a0 = __float_as_uint(xr[cc]);
                unsigned a1 = __float_as_uint(xr[8 * 68 + cc]);
                unsigned a2 = __float_as_uint(xr[cc + 4]);
                unsigned a3 = __float_as_uint(xr[8 * 68 + cc + 4]);
                int kg = half * 64 + ks * 8 + lm4;
                const float* bcol = w1b + kg * 72;
                #pragma unroll
                for (int nt = 0; nt < 8; nt++) {
                    unsigned b0 = __float_as_uint(bcol[nt * 8 + l4]);
                    unsigned b1f = __float_as_uint(bcol[4 * 72 + nt * 8 + l4]);
                    MMA_TF32(acc[nt][0], acc[nt][1], acc[nt][2], acc[nt][3],
                             a0, a1, a2, a3, b0, b1f);
                }
            }
        }

        // ---- relu + score from fragments ----
        float sc0 = 0.f, sc1 = 0.f;
        #pragma unroll
        for (int nt = 0; nt < 8; nt++) {
            int col0 = nt * 8 + lm4 * 2;
            float u0 = bb[64 + col0], u1v = bb[64 + col0 + 1];
            acc[nt][0] = fmaxf(acc[nt][0], 0.f);
            acc[nt][1] = fmaxf(acc[nt][1], 0.f);
            acc[nt][2] = fmaxf(acc[nt][2], 0.f);
            acc[nt][3] = fmaxf(acc[nt][3], 0.f);
            sc0 = fmaf(acc[nt][0], u0, fmaf(acc[nt][1], u1v, sc0));
            sc1 = fmaf(acc[nt][2], u0, fmaf(acc[nt][3], u1v, sc1));
        }
        sc0 += __shfl_down_sync(0xffffffffu, sc0, 2, 4);
        sc0 += __shfl_down_sync(0xffffffffu, sc0, 1, 4);
        sc1 += __shfl_down_sync(0xffffffffu, sc1, 2, 4);
        sc1 += __shfl_down_sync(0xffffffffu, sc1, 1, 4);
        if (lm4 == 0) {
            int node = base + tw * 16 + l4;
            if (node < NN)     out[node]     = sc0 + c1;
            if (node + 8 < NN) out[node + 8] = sc1 + c1;
        }

        // ---- write h1 (tf32) to smem — scalar stores (stride 65 is odd) ----
        __syncthreads();
        {
            float* h0 = hsf + (tw * 16 + l4) * 65;
            float* h8 = h0 + 8 * 65;
            #pragma unroll
            for (int nt = 0; nt < 8; nt++) {
                int col0 = nt * 8 + lm4 * 2;
                h0[col0]     = __uint_as_float(cvt_tf32(acc[nt][0]));
                h0[col0 + 1] = __uint_as_float(cvt_tf32(acc[nt][1]));
                h8[col0]     = __uint_as_float(cvt_tf32(acc[nt][2]));
                h8[col0 + 1] = __uint_as_float(cvt_tf32(acc[nt][3]));
            }
        }
        __syncthreads();

        // ---- heads: 16 warps = (m-pair mp, n-half nh) ----
        {
            const int mp = tw & 7, nh = tw >> 3;
            unsigned Af[2][8][4];
            #pragma unroll
            for (int mt = 0; mt < 2; mt++) {
                const float* h0 = hsf + (mp * 32 + mt * 16 + l4) * 65;
                const float* h1r = h0 + 8 * 65;
                #pragma unroll
                for (int ks = 0; ks < 8; ks++) {
                    int cc = ks * 8 + lm4;
                    Af[mt][ks][0] = __float_as_uint(h0[cc]);
                    Af[mt][ks][1] = __float_as_uint(h1r[cc]);
                    Af[mt][ks][2] = __float_as_uint(h0[cc + 4]);
                    Af[mt][ks][3] = __float_as_uint(h1r[cc + 4]);
                }
            }
            const int n0g = base + mp * 32 + l4;
            float vs[4] = {0.f, 0.f, 0.f, 0.f};
            #pragma unroll 1
            for (int nt = nh * 12; nt < nh * 12 + 12; nt++) {
                int f192 = nt * 8 + 2 * lm4;
                float2 bias = *(const float2*)(bb + 128 + f192);
                unsigned Bf[8][2];
                const float* bcol = atb2 + nt * 8 + l4;
                #pragma unroll
                for (int ks = 0; ks < 8; ks++) {
                    Bf[ks][0] = __float_as_uint(bcol[(ks * 8 + lm4) * 200]);
                    Bf[ks][1] = __float_as_uint(bcol[(ks * 8 + lm4 + 4) * 200]);
                }
                int feat = f192 & 63;
                #pragma unroll
                for (int mt = 0; mt < 2; mt++) {
                    float d0 = bias.x, d1 = bias.y, d2 = bias.x, d3 = bias.y;
                    #pragma unroll
                    for (int ks = 0; ks < 8; ks++)
                        MMA_TF32(d0, d1, d2, d3,
                                 Af[mt][ks][0], Af[mt][ks][1], Af[mt][ks][2], Af[mt][ks][3],
                                 Bf[ks][0], Bf[ks][1]);
                    int node = n0g + mt * 16;
                    if (f192 < 128) {
                        // k or q head -> fp8 e4m3
                        unsigned char* dp = (f192 < 64) ? g_k8 : g_q8;
                        if (node < NN)
                            *(unsigned short*)(dp + (size_t)node * 64 + feat) = pack_e4m3x2(d0, d1);
                        if (node + 8 < NN)
                            *(unsigned short*)(dp + (size_t)(node + 8) * 64 + feat) = pack_e4m3x2(d2, d3);
                    } else {
                        // v head -> f16 + exact vsum (fp32)
                        vs[mt * 2]     += d0 + d1;
                        vs[mt * 2 + 1] += d2 + d3;
                        if (node < NN)
                            *(unsigned*)(g_vh + (size_t)node * 64 + feat) = pack_h2(d0, d1);
                        if (node + 8 < NN)
                            *(unsigned*)(g_vh + (size_t)(node + 8) * 64 + feat) = pack_h2(d2, d3);
                    }
                }
            }
            if (nh == 1) {
                #pragma unroll
                for (int t = 0; t < 4; t++) {
                    vs[t] += __shfl_down_sync(0xffffffffu, vs[t], 2, 4);
                    vs[t] += __shfl_down_sync(0xffffffffu, vs[t], 1, 4);
                }
                if (lm4 == 0) {
                    #pragma unroll
                    for (int mt = 0; mt < 2; mt++) {
                        int node = n0g + mt * 16;
                        if (node < NN)     g_vsum[node]     = vs[mt * 2];
                        if (node + 8 < NN) g_vsum[node + 8] = vs[mt * 2 + 1];
                    }
                }
            }
        }
    }
}

// ---------------- edge kernel: 4 lanes/edge, fp8 k/q + f16 v ----------------
// Per 4 feats: kw/qw = 4 e4m3 bytes; v01/v23 = two f16x2.
__device__ __forceinline__ void grp4(unsigned kw, unsigned qw,
                                     unsigned v01, unsigned v23, __half2& acc) {
    unsigned short k0 = (unsigned short)(kw & 0xffffu), k1 = (unsigned short)(kw >> 16);
    unsigned short q0 = (unsigned short)(qw & 0xffffu), q1 = (unsigned short)(qw >> 16);
    unsigned kf0, kf1, qf0, qf1, t0, t1;
    asm("cvt.rn.f16x2.e4m3x2 %0, %1;" : "=r"(kf0) : "h"(k0));
    asm("cvt.rn.f16x2.e4m3x2 %0, %1;" : "=r"(kf1) : "h"(k1));
    asm("cvt.rn.f16x2.e4m3x2 %0, %1;" : "=r"(qf0) : "h"(q0));
    asm("cvt.rn.f16x2.e4m3x2 %0, %1;" : "=r"(qf1) : "h"(q1));
    __half2 s0 = __hadd2(*(__half2*)&kf0, *(__half2*)&qf0);
    __half2 s1 = __hadd2(*(__half2*)&kf1, *(__half2*)&qf1);
    asm("tanh.approx.f16x2 %0, %1;" : "=r"(t0) : "r"(*(unsigned*)&s0));
    asm("tanh.approx.f16x2 %0, %1;" : "=r"(t1) : "r"(*(unsigned*)&s1));
    acc = __hfma2(*(__half2*)&t0, *(__half2*)&v01, acc);
    acc = __hfma2(*(__half2*)&t1, *(__half2*)&v23, acc);
}

__global__ __launch_bounds__(256)
void edge_kernel(const int* __restrict__ ei, float* __restrict__ out)
{
    int t = blockIdx.x * 256 + threadIdx.x;
    int e = t >> 2;
    if (e >= EE) return;
    int sub = t & 3;

    int src = ei[e];
    int dst = ei[EE + e];

    // lane covers feats [sub*16, sub*16+16)
    uint4 kk = *(const uint4*)(g_k8 + (size_t)dst * 64 + sub * 16);
    uint4 qq = *(const uint4*)(g_q8 + (size_t)src * 64 + sub * 16);
    const uint4* vp = (const uint4*)(g_vh + (size_t)src * 64 + sub * 16);
    uint4 v0 = vp[0], v1 = vp[1];

    __half2 a0 = __floats2half2_rn(0.f, 0.f);
    __half2 a1 = __floats2half2_rn(0.f, 0.f);
    grp4(kk.x, qq.x, v0.x, v0.y, a0);
    grp4(kk.y, qq.y, v0.z, v0.w, a1);
    grp4(kk.z, qq.z, v1.x, v1.y, a0);
    grp4(kk.w, qq.w, v1.z, v1.w, a1);

    float2 f = __half22float2(__hadd2(a0, a1));
    float s = f.x + f.y;

    s += __shfl_down_sync(0xffffffffu, s, 2, 4);
    s += __shfl_down_sync(0xffffffffu, s, 1, 4);
    if (sub == 0) {
        // message = 0.5*(sum t.v + sum v)   (vsum exact fp32)
        atomicAdd(out + dst, 0.5f * (s + g_vsum[src]));
    }
}

extern "C" void kernel_launch(void* const* d_in, const int* in_sizes, int n_in,
                              void* d_out, int out_size)
{
    const float* x      = (const float*)d_in[0];
    const int*   ei     = (const int*)d_in[1];
    const float* W1     = (const float*)d_in[2];
    const float* b1     = (const float*)d_in[3];
    const float* W2     = (const float*)d_in[4];
    const float* b2     = (const float*)d_in[5];
    const float* Wk     = (const float*)d_in[6];
    const float* bk     = (const float*)d_in[7];
    const float* Wq     = (const float*)d_in[8];
    const float* bq     = (const float*)d_in[9];
    const float* Wv     = (const float*)d_in[10];
    const float* bv     = (const float*)d_in[11];
    const float* Ws     = (const float*)d_in[12];
    const float* b_gate = (const float*)d_in[13];
    const float* Wsc    = (const float*)d_in[14];
    const float* bsc    = (const float*)d_in[15];
    float* out = (float*)d_out;

    size_t smemf = 39744 * sizeof(float);   // 155.3 KB
    cudaFuncSetAttribute(node_fused, cudaFuncAttributeMaxDynamicSharedMemorySize, (int)smemf);

    prec<<<16, 256>>>(W2, b2, Wk, bk, Wq, bq, Wv, bv, Ws, b_gate, Wsc, bsc);
    node_fused<<<148, 512, smemf>>>(x, W1, b1, out);
    edge_kernel<<<(EE * 4) / 256, 256>>>(ei, out);   // 25000 blocks
}